// round 15
// baseline (speedup 1.0000x reference)
#include <cuda_runtime.h>
#include <cuda_bf16.h>
#include <cfloat>

// Problem constants (fixed by setup_inputs)
#define BATCH 32
#define CH    512
#define TLEN  128
#define NROI  128
#define OBINS 64
#define BINSZ 8                              // CH / OBINS
#define NROIS_TOTAL (BATCH * NROI)           // 4096
#define POOLED_ELEMS (NROIS_TOTAL * OBINS)   // 262144

#define SPLIT_O 8                            // o-groups per batch
#define OB (OBINS / SPLIT_O)                 // 8 bins per block (1 per warp)
#define NTHREADS 256
#define LVPITCH 132                          // 128 t + pad, 528B row (16B-mult)

__device__ __forceinline__ float4 f4max(float4 a, float4 b) {
    float4 r;
    r.x = fmaxf(a.x, b.x); r.y = fmaxf(a.y, b.y);
    r.z = fmaxf(a.z, b.z); r.w = fmaxf(a.w, b.w);
    return r;
}

// Fused kernel, warp-autonomous: grid = 32x8 = 256 blocks, 256 threads.
// Warp w owns bin og*8+w. Lane = t-quad. Pipeline per warp (no block sync):
//   load 8 channels -> fold to L0 quad (regs) -> build sparse-max levels
//   L1..L4 via shuffles -> store all 5 levels -> __syncwarp ->
//   each output = max of 2 table lookups. One __syncthreads only for the
//   coalescing transpose of the output tile.
// Ordering note (measured): feature LDG burst must issue FIRST; the tois
// loads overlap under the shuffle cascade where their latency is free.
__global__ void __launch_bounds__(NTHREADS, 4)
roipool_fused(const float* __restrict__ feat,
              const int* __restrict__ tois,
              float* __restrict__ out) {
    const int tid = threadIdx.x;
    const int w   = tid >> 5;                // warp = bin within group
    const int l   = tid & 31;                // lane = t-quad
    const int b   = blockIdx.x >> 3;         // batch
    const int og  = blockIdx.x & 7;          // bin-group

    __shared__ float lv[5 * OB * LVPITCH];   // [k][w][t], ~21 KB
    __shared__ float st[NROI * (OB + 1)];    // staging [rl][o] pitch 9, 4.6 KB

    // ---- Phase 1: load 8 channels of this bin at this t-quad, fold ----
    const float4* p = (const float4*)(feat
        + ((size_t)b * CH + (size_t)(og * OB + w) * BINSZ) * TLEN) + l;
    float4 v0 = p[0 * 32], v1 = p[1 * 32], v2 = p[2 * 32], v3 = p[3 * 32];
    float4 v4 = p[4 * 32], v5 = p[5 * 32], v6 = p[6 * 32], v7 = p[7 * 32];
    float4 a = f4max(f4max(f4max(v0, v1), f4max(v2, v3)),
                     f4max(f4max(v4, v5), f4max(v6, v7)));   // L0[4l..4l+3]

    // ---- Build sparse-max levels in registers via shuffles ----
    const unsigned FULL = 0xffffffffu;
    // L1[t] = max(L0[t], L0[t+1])
    float nx = __shfl_down_sync(FULL, a.x, 1);
    float4 bq = make_float4(fmaxf(a.x, a.y), fmaxf(a.y, a.z),
                            fmaxf(a.z, a.w), fmaxf(a.w, nx));
    // L2[t] = max(L1[t], L1[t+2])
    float nb0 = __shfl_down_sync(FULL, bq.x, 1);
    float nb1 = __shfl_down_sync(FULL, bq.y, 1);
    float4 cq = make_float4(fmaxf(bq.x, bq.z), fmaxf(bq.y, bq.w),
                            fmaxf(bq.z, nb0), fmaxf(bq.w, nb1));
    // L3[t] = max(L2[t], L2[t+4])  (next lane's quad)
    float4 nc;
    nc.x = __shfl_down_sync(FULL, cq.x, 1); nc.y = __shfl_down_sync(FULL, cq.y, 1);
    nc.z = __shfl_down_sync(FULL, cq.z, 1); nc.w = __shfl_down_sync(FULL, cq.w, 1);
    float4 dq = f4max(cq, nc);
    // L4[t] = max(L3[t], L3[t+8])  (lane+2's quad)
    float4 nd;
    nd.x = __shfl_down_sync(FULL, dq.x, 2); nd.y = __shfl_down_sync(FULL, dq.y, 2);
    nd.z = __shfl_down_sync(FULL, dq.z, 2); nd.w = __shfl_down_sync(FULL, dq.w, 2);
    float4 eq = f4max(dq, nd);
    // (Clamped-shuffle garbage lives only at t > 128-2^k, never queried.)

    // Store levels: STS.128, lane-consecutive granules -> conflict-free.
    *(float4*)&lv[(0 * OB + w) * LVPITCH + 4 * l] = a;
    *(float4*)&lv[(1 * OB + w) * LVPITCH + 4 * l] = bq;
    *(float4*)&lv[(2 * OB + w) * LVPITCH + 4 * l] = cq;
    *(float4*)&lv[(3 * OB + w) * LVPITCH + 4 * l] = dq;
    *(float4*)&lv[(4 * OB + w) * LVPITCH + 4 * l] = eq;
    __syncwarp();

    // ---- Phase 2: 128 ROIs for this bin, 4 per lane, 2 lookups each ----
    const int2* tp = (const int2*)(tois) + b * NROI;
#pragma unroll
    for (int i = 0; i < 4; i++) {
        const int rl = l + 32 * i;
        const int2 se = __ldg(&tp[rl]);
        const int len = se.y - se.x;         // 1..16
        const int k = 31 - __clz(len);       // floor(log2 len), 0..4
        const float* Lk = &lv[(k * OB + w) * LVPITCH];
        float m = fmaxf(Lk[se.x], Lk[se.y - (1 << k)]);
        st[rl * (OB + 1) + w] = m;           // 9l mod 32 -> conflict-free
    }
    __syncthreads();

    // ---- Coalescing writeout: 1024 floats, 4 per thread ----
#pragma unroll
    for (int idx = tid; idx < NROI * OB; idx += NTHREADS) {
        const int rl = idx >> 3;
        const int o  = idx & 7;
        out[(size_t)(b * NROI + rl) * OBINS + og * OB + o] = st[rl * (OB + 1) + o];
    }

    // ---- offsets tail (float-encoded in the unified f32 output buffer) ----
    if (blockIdx.x == 0 && tid < BATCH) {
        out[POOLED_ELEMS + tid] = (float)((tid + 1) * NROI);
    }
}

extern "C" void kernel_launch(void* const* d_in, const int* in_sizes, int n_in,
                              void* d_out, int out_size) {
    const float* feat = (const float*)d_in[0];   // [32, 512, 128] f32
    const int*   tois = (const int*)d_in[1];     // [32, 128, 2] i32
    float* out = (float*)d_out;

    roipool_fused<<<BATCH * SPLIT_O, NTHREADS>>>(feat, tois, out);
}

// round 16
// speedup vs baseline: 1.1020x; 1.1020x over previous
#include <cuda_runtime.h>
#include <cuda_bf16.h>
#include <cfloat>

// Problem constants (fixed by setup_inputs)
#define BATCH 32
#define CH    512
#define TLEN  128
#define NROI  128
#define OBINS 64
#define BINSZ 8                              // CH / OBINS
#define NROIS_TOTAL (BATCH * NROI)           // 4096
#define POOLED_ELEMS (NROIS_TOTAL * OBINS)   // 262144

#define SPLIT_O 8                            // o-groups per batch
#define OB (OBINS / SPLIT_O)                 // 8 bins per block (1 per warp)
#define NTHREADS 256
#define LVPITCH 132                          // 128 t + pad, 528B row (16B-mult)
#define STPITCH (OB + 1)                     // 9, coprime with 32

__device__ __forceinline__ float4 f4max(float4 a, float4 b) {
    float4 r;
    r.x = fmaxf(a.x, b.x); r.y = fmaxf(a.y, b.y);
    r.z = fmaxf(a.z, b.z); r.w = fmaxf(a.w, b.w);
    return r;
}

// Final kernel (R7 structure). Grid = 32x8 = 256 blocks, 256 threads.
// Warp w owns bin og*8+w. Lane = t-quad. Per warp, no block sync until the
// output transpose:
//   8x LDG.128 burst (the bin's 8 channels) -> fold to L0 in regs ->
//   build sparse range-max levels L1..L4 via shuffles -> store 5 levels to
//   smem -> each ROI answered with 2 lookups + 1 fmax (tois loads overlap
//   under the shuffle cascade) -> coalesced float4 writeout.
// Ordering note (measured): the feature LDG burst must issue FIRST; hoisting
// the tois loads above it lengthens the exposed latency chain (R14).
__global__ void __launch_bounds__(NTHREADS, 4)
roipool_fused(const float* __restrict__ feat,
              const int* __restrict__ tois,
              float* __restrict__ out) {
    const int tid = threadIdx.x;
    const int w   = tid >> 5;                // warp = bin within group
    const int l   = tid & 31;                // lane = t-quad
    const int b   = blockIdx.x >> 3;         // batch
    const int og  = blockIdx.x & 7;          // bin-group

    __shared__ alignas(16) float lv[5 * OB * LVPITCH];  // [k][w][t], ~21 KB
    __shared__ float st[NROI * STPITCH];                // staging, 4.6 KB

    // ---- Phase 1: load 8 channels of this bin at this t-quad, fold ----
    const float4* p = (const float4*)(feat
        + ((size_t)b * CH + (size_t)(og * OB + w) * BINSZ) * TLEN) + l;
    float4 v0 = p[0 * 32], v1 = p[1 * 32], v2 = p[2 * 32], v3 = p[3 * 32];
    float4 v4 = p[4 * 32], v5 = p[5 * 32], v6 = p[6 * 32], v7 = p[7 * 32];
    float4 a = f4max(f4max(f4max(v0, v1), f4max(v2, v3)),
                     f4max(f4max(v4, v5), f4max(v6, v7)));   // L0[4l..4l+3]

    // ---- Build sparse-max levels in registers via shuffles ----
    const unsigned FULL = 0xffffffffu;
    // L1[t] = max(L0[t], L0[t+1])
    float nx = __shfl_down_sync(FULL, a.x, 1);
    float4 bq = make_float4(fmaxf(a.x, a.y), fmaxf(a.y, a.z),
                            fmaxf(a.z, a.w), fmaxf(a.w, nx));
    // L2[t] = max(L1[t], L1[t+2])
    float nb0 = __shfl_down_sync(FULL, bq.x, 1);
    float nb1 = __shfl_down_sync(FULL, bq.y, 1);
    float4 cq = make_float4(fmaxf(bq.x, bq.z), fmaxf(bq.y, bq.w),
                            fmaxf(bq.z, nb0), fmaxf(bq.w, nb1));
    // L3[t] = max(L2[t], L2[t+4])  (next lane's quad)
    float4 nc;
    nc.x = __shfl_down_sync(FULL, cq.x, 1); nc.y = __shfl_down_sync(FULL, cq.y, 1);
    nc.z = __shfl_down_sync(FULL, cq.z, 1); nc.w = __shfl_down_sync(FULL, cq.w, 1);
    float4 dq = f4max(cq, nc);
    // L4[t] = max(L3[t], L3[t+8])  (lane+2's quad)
    float4 nd;
    nd.x = __shfl_down_sync(FULL, dq.x, 2); nd.y = __shfl_down_sync(FULL, dq.y, 2);
    nd.z = __shfl_down_sync(FULL, dq.z, 2); nd.w = __shfl_down_sync(FULL, dq.w, 2);
    float4 eq = f4max(dq, nd);
    // (Clamped-shuffle garbage lives only at t > 128-2^k; a level-k lookup
    //  always has t <= 128-2^k, so it is never queried.)

    // Store levels: STS.128, lane-consecutive granules -> conflict-free.
    *(float4*)&lv[(0 * OB + w) * LVPITCH + 4 * l] = a;
    *(float4*)&lv[(1 * OB + w) * LVPITCH + 4 * l] = bq;
    *(float4*)&lv[(2 * OB + w) * LVPITCH + 4 * l] = cq;
    *(float4*)&lv[(3 * OB + w) * LVPITCH + 4 * l] = dq;
    *(float4*)&lv[(4 * OB + w) * LVPITCH + 4 * l] = eq;
    __syncwarp();

    // ---- Phase 2: 128 ROIs for this bin, 4 per lane, 2 lookups each ----
    const int2* tp = (const int2*)(tois) + b * NROI;
#pragma unroll
    for (int i = 0; i < 4; i++) {
        const int rl = l + 32 * i;
        const int2 se = __ldg(&tp[rl]);
        const int len = se.y - se.x;         // 1..16
        const int k = 31 - __clz(len);       // floor(log2 len), 0..4
        const float* Lk = &lv[(k * OB + w) * LVPITCH];
        float m = fmaxf(Lk[se.x], Lk[se.y - (1 << k)]);
        st[rl * STPITCH + w] = m;            // 9l mod 32 -> conflict-free
    }
    __syncthreads();

    // ---- Coalescing writeout: 1024 floats, one float4 per half-thread ----
    {
        const int r = tid >> 1;              // ROI 0..127
        const int h = (tid & 1) * 4;         // bin half
        float4 v = make_float4(st[r * STPITCH + h + 0], st[r * STPITCH + h + 1],
                               st[r * STPITCH + h + 2], st[r * STPITCH + h + 3]);
        *(float4*)&out[(size_t)(b * NROI + r) * OBINS + og * OB + h] = v;
    }

    // ---- offsets tail (float-encoded in the unified f32 output buffer) ----
    if (blockIdx.x == 0 && tid < BATCH) {
        out[POOLED_ELEMS + tid] = (float)((tid + 1) * NROI);
    }
}

extern "C" void kernel_launch(void* const* d_in, const int* in_sizes, int n_in,
                              void* d_out, int out_size) {
    const float* feat = (const float*)d_in[0];   // [32, 512, 128] f32
    const int*   tois = (const int*)d_in[1];     // [32, 128, 2] i32
    float* out = (float*)d_out;

    roipool_fused<<<BATCH * SPLIT_O, NTHREADS>>>(feat, tois, out);
}

// round 17
// speedup vs baseline: 1.1250x; 1.0208x over previous
#include <cuda_runtime.h>
#include <cuda_bf16.h>
#include <cfloat>

// Problem constants (fixed by setup_inputs)
#define BATCH 32
#define CH    512
#define TLEN  128
#define NROI  128
#define OBINS 64
#define BINSZ 8                              // CH / OBINS
#define NROIS_TOTAL (BATCH * NROI)           // 4096
#define POOLED_ELEMS (NROIS_TOTAL * OBINS)   // 262144

#define SPLIT_O 8                            // o-groups per batch
#define OB (OBINS / SPLIT_O)                 // 8 bins per block (1 per warp)
#define NTHREADS 256
#define LVPITCH 132                          // 128 t + pad, 528B row (16B-mult)
#define STPITCH (OB + 1)                     // 9, coprime with 32

__device__ __forceinline__ float4 f4max(float4 a, float4 b) {
    float4 r;
    r.x = fmaxf(a.x, b.x); r.y = fmaxf(a.y, b.y);
    r.z = fmaxf(a.z, b.z); r.w = fmaxf(a.w, b.w);
    return r;
}

// Final kernel. Grid = 32x8 = 256 blocks, 256 threads.
// Warp w owns bin og*8+w. Lane = t-quad. Per warp, no block sync until the
// output transpose:
//   8x LDG.128 burst (the bin's 8 channels) -> fold to L0 in regs ->
//   build sparse range-max levels L1..L4 via shuffles -> store 5 levels to
//   smem -> each ROI answered with 2 lookups + 1 fmax (tois loads overlap
//   under the shuffle cascade) -> coalesced float4 writeout.
// Ordering note (measured): the feature LDG burst must issue FIRST; hoisting
// the tois loads above it lengthens the exposed latency chain (R14).
__global__ void __launch_bounds__(NTHREADS, 4)
roipool_fused(const float* __restrict__ feat,
              const int* __restrict__ tois,
              float* __restrict__ out) {
    const int tid = threadIdx.x;
    const int w   = tid >> 5;                // warp = bin within group
    const int l   = tid & 31;                // lane = t-quad
    const int b   = blockIdx.x >> 3;         // batch
    const int og  = blockIdx.x & 7;          // bin-group

    __shared__ alignas(16) float lv[5 * OB * LVPITCH];  // [k][w][t], ~21 KB
    __shared__ float st[NROI * STPITCH];                // staging, 4.6 KB

    // ---- Phase 1: load 8 channels of this bin at this t-quad, fold ----
    const float4* p = (const float4*)(feat
        + ((size_t)b * CH + (size_t)(og * OB + w) * BINSZ) * TLEN) + l;
    float4 v0 = p[0 * 32], v1 = p[1 * 32], v2 = p[2 * 32], v3 = p[3 * 32];
    float4 v4 = p[4 * 32], v5 = p[5 * 32], v6 = p[6 * 32], v7 = p[7 * 32];
    float4 a = f4max(f4max(f4max(v0, v1), f4max(v2, v3)),
                     f4max(f4max(v4, v5), f4max(v6, v7)));   // L0[4l..4l+3]

    // ---- Build sparse-max levels in registers via shuffles ----
    const unsigned FULL = 0xffffffffu;
    // L1[t] = max(L0[t], L0[t+1])
    float nx = __shfl_down_sync(FULL, a.x, 1);
    float4 bq = make_float4(fmaxf(a.x, a.y), fmaxf(a.y, a.z),
                            fmaxf(a.z, a.w), fmaxf(a.w, nx));
    // L2[t] = max(L1[t], L1[t+2])
    float nb0 = __shfl_down_sync(FULL, bq.x, 1);
    float nb1 = __shfl_down_sync(FULL, bq.y, 1);
    float4 cq = make_float4(fmaxf(bq.x, bq.z), fmaxf(bq.y, bq.w),
                            fmaxf(bq.z, nb0), fmaxf(bq.w, nb1));
    // L3[t] = max(L2[t], L2[t+4])  (next lane's quad)
    float4 nc;
    nc.x = __shfl_down_sync(FULL, cq.x, 1); nc.y = __shfl_down_sync(FULL, cq.y, 1);
    nc.z = __shfl_down_sync(FULL, cq.z, 1); nc.w = __shfl_down_sync(FULL, cq.w, 1);
    float4 dq = f4max(cq, nc);
    // L4[t] = max(L3[t], L3[t+8])  (lane+2's quad)
    float4 nd;
    nd.x = __shfl_down_sync(FULL, dq.x, 2); nd.y = __shfl_down_sync(FULL, dq.y, 2);
    nd.z = __shfl_down_sync(FULL, dq.z, 2); nd.w = __shfl_down_sync(FULL, dq.w, 2);
    float4 eq = f4max(dq, nd);
    // (Clamped-shuffle garbage lives only at t > 128-2^k; a level-k lookup
    //  always has t <= 128-2^k, so it is never queried.)

    // Store levels: STS.128, lane-consecutive granules -> conflict-free.
    *(float4*)&lv[(0 * OB + w) * LVPITCH + 4 * l] = a;
    *(float4*)&lv[(1 * OB + w) * LVPITCH + 4 * l] = bq;
    *(float4*)&lv[(2 * OB + w) * LVPITCH + 4 * l] = cq;
    *(float4*)&lv[(3 * OB + w) * LVPITCH + 4 * l] = dq;
    *(float4*)&lv[(4 * OB + w) * LVPITCH + 4 * l] = eq;
    __syncwarp();

    // ---- Phase 2: 128 ROIs for this bin, 4 per lane, 2 lookups each ----
    const int2* tp = (const int2*)(tois) + b * NROI;
#pragma unroll
    for (int i = 0; i < 4; i++) {
        const int rl = l + 32 * i;
        const int2 se = __ldg(&tp[rl]);
        const int len = se.y - se.x;         // 1..16
        const int k = 31 - __clz(len);       // floor(log2 len), 0..4
        const float* Lk = &lv[(k * OB + w) * LVPITCH];
        float m = fmaxf(Lk[se.x], Lk[se.y - (1 << k)]);
        st[rl * STPITCH + w] = m;            // 9l mod 32 -> conflict-free
    }
    __syncthreads();

    // ---- Coalescing writeout: 1024 floats, one float4 per half-thread ----
    {
        const int r = tid >> 1;              // ROI 0..127
        const int h = (tid & 1) * 4;         // bin half
        float4 v = make_float4(st[r * STPITCH + h + 0], st[r * STPITCH + h + 1],
                               st[r * STPITCH + h + 2], st[r * STPITCH + h + 3]);
        *(float4*)&out[(size_t)(b * NROI + r) * OBINS + og * OB + h] = v;
    }

    // ---- offsets tail (float-encoded in the unified f32 output buffer) ----
    if (blockIdx.x == 0 && tid < BATCH) {
        out[POOLED_ELEMS + tid] = (float)((tid + 1) * NROI);
    }
}

extern "C" void kernel_launch(void* const* d_in, const int* in_sizes, int n_in,
                              void* d_out, int out_size) {
    const float* feat = (const float*)d_in[0];   // [32, 512, 128] f32
    const int*   tois = (const int*)d_in[1];     // [32, 128, 2] i32
    float* out = (float*)d_out;

    roipool_fused<<<BATCH * SPLIT_O, NTHREADS>>>(feat, tois, out);
}